// round 3
// baseline (speedup 1.0000x reference)
#include <cuda_runtime.h>

// Problem constants
#define K_CODES 1024
#define D_DIM   64
#define B_SZ    16
#define T_LEN   8192
#define N_VEC   (B_SZ * T_LEN)   // 131072 vectors
#define CHUNK   128              // codes cached in smem per chunk
#define TPB     256

typedef unsigned long long u64;

// Packed fp32x2 ops (Blackwell sm_103a; PTX-only, ptxas never auto-fuses)
#define FMA_X2(d, a, b, c) \
    asm("fma.rn.f32x2 %0, %1, %2, %3;" : "=l"(d) : "l"(a), "l"(b), "l"(c))
#define ADD_X2(d, a, b) \
    asm("add.rn.f32x2 %0, %1, %2;" : "=l"(d) : "l"(a), "l"(b))
#define PACK_X2(d, lo, hi) \
    asm("mov.b64 %0, {%1, %2};" : "=l"(d) : "f"(lo), "f"(hi))
#define UNPACK_X2(lo, hi, s) \
    asm("mov.b64 {%0, %1}, %2;" : "=f"(lo), "=f"(hi) : "l"(s))
// 16B shared load as two packed f32x2 operands (one LDS.128)
#define LDS_V2U64(p0, p1, addr) \
    asm("ld.shared.v2.u64 {%0, %1}, [%2];" : "=l"(p0), "=l"(p1) : "r"(addr))

// Scratch (allocation-free rule -> __device__ globals)
__device__ float g_dw[K_CODES * D_DIM];
__device__ int   g_counts[K_CODES];
__device__ float g_enorm[K_CODES];

__global__ void zero_kernel() {
    int i = blockIdx.x * blockDim.x + threadIdx.x;
    if (i < K_CODES * D_DIM) g_dw[i] = 0.0f;
    if (i < K_CODES)         g_counts[i] = 0;
}

__global__ void enorm_kernel(const float* __restrict__ emb) {
    int c = blockIdx.x * blockDim.x + threadIdx.x;
    if (c < K_CODES) {
        const float* e = emb + c * D_DIM;
        float s0 = 0.f, s1 = 0.f, s2 = 0.f, s3 = 0.f;
        #pragma unroll
        for (int d = 0; d < D_DIM; d += 4) {
            float v0 = e[d + 0], v1 = e[d + 1], v2 = e[d + 2], v3 = e[d + 3];
            s0 = fmaf(v0, v0, s0);
            s1 = fmaf(v1, v1, s1);
            s2 = fmaf(v2, v2, s2);
            s3 = fmaf(v3, v3, s3);
        }
        g_enorm[c] = (s0 + s1) + (s2 + s3);
    }
}

// One thread per vector. x vector lives ONLY in packed f32x2 form (32 u64
// regs) across the main loop; scalars are re-derived in the epilogue.
// Embeddings streamed through shared memory in CHUNK-code tiles; all 32
// lanes of a warp read the same code row -> broadcast, conflict-free LDS.128.
// Dot product via packed fma.rn.f32x2: 32 FFMA2 per code instead of 64 FFMA.
__global__ __launch_bounds__(TPB) void assign_kernel(
    const float* __restrict__ x,
    const float* __restrict__ emb,
    float* __restrict__ outq)
{
    __shared__ float es[CHUNK][D_DIM];   // 32 KB
    __shared__ float en[CHUNK];

    const int n = blockIdx.x * TPB + threadIdx.x;   // vector index = b*T + t
    const int b = n >> 13;                          // / 8192
    const int t = n & (T_LEN - 1);

    // Load + pack x vector: per d, warp lanes hit consecutive t -> coalesced.
    // Only the packed form stays live through the main loop.
    u64 xp[D_DIM / 2];
    #pragma unroll
    for (int i = 0; i < D_DIM / 2; i++) {
        float lo = x[((size_t)((b << 6) + 2 * i + 0)) * T_LEN + t];
        float hi = x[((size_t)((b << 6) + 2 * i + 1)) * T_LEN + t];
        PACK_X2(xp[i], lo, hi);
    }

    const unsigned es_base = (unsigned)__cvta_generic_to_shared(&es[0][0]);

    float best  = 3.402823466e38f;
    int   bestc = 0;

    for (int c0 = 0; c0 < K_CODES; c0 += CHUNK) {
        __syncthreads();
        {   // cooperative chunk load: CHUNK*D_DIM floats, fully coalesced
            const float4* src = (const float4*)(emb + (size_t)c0 * D_DIM);
            float4* dst = (float4*)&es[0][0];
            #pragma unroll
            for (int i = threadIdx.x; i < CHUNK * D_DIM / 4; i += TPB)
                dst[i] = src[i];
            if (threadIdx.x < CHUNK)
                en[threadIdx.x] = g_enorm[c0 + threadIdx.x];
        }
        __syncthreads();

        #pragma unroll 2
        for (int c = 0; c < CHUNK; c++) {
            const unsigned row = es_base + c * (D_DIM * 4);
            u64 a0 = 0ull, a1 = 0ull, a2 = 0ull, a3 = 0ull;
            #pragma unroll
            for (int q = 0; q < D_DIM / 16; q++) {      // 4 iters x 16 elems
                u64 e0, e1, e2, e3, e4, e5, e6, e7;
                LDS_V2U64(e0, e1, row + q * 64 +  0);
                LDS_V2U64(e2, e3, row + q * 64 + 16);
                LDS_V2U64(e4, e5, row + q * 64 + 32);
                LDS_V2U64(e6, e7, row + q * 64 + 48);
                FMA_X2(a0, xp[8 * q + 0], e0, a0);
                FMA_X2(a1, xp[8 * q + 1], e1, a1);
                FMA_X2(a2, xp[8 * q + 2], e2, a2);
                FMA_X2(a3, xp[8 * q + 3], e3, a3);
                FMA_X2(a0, xp[8 * q + 4], e4, a0);
                FMA_X2(a1, xp[8 * q + 5], e5, a1);
                FMA_X2(a2, xp[8 * q + 6], e6, a2);
                FMA_X2(a3, xp[8 * q + 7], e7, a3);
            }
            ADD_X2(a0, a0, a1);
            ADD_X2(a2, a2, a3);
            ADD_X2(a0, a0, a2);
            float lo, hi;
            UNPACK_X2(lo, hi, a0);
            float dot = lo + hi;
            float s = fmaf(-2.0f, dot, en[c]);   // ||x||^2 dropped: same argmin
            if (s < best) { best = s; bestc = c0 + c; }  // strict <: first min
        }
    }

    // Epilogue. Quantized output out[b][d][t] = emb[bestc][d]: read the code
    // row with float4 (16 LDG.128 instead of 64 LDG.32); stores stay scalar
    // (d-stride = T_LEN) but are coalesced across lanes (t). dw/counts via
    // global float atomics (rounding noise << 1e-3 tolerance).
    const float4* eb4 = (const float4*)(emb + (size_t)bestc * D_DIM);
    float* dwp = g_dw + (size_t)bestc * D_DIM;
    float* op  = outq + (size_t)(b << 6) * T_LEN + t;
    #pragma unroll
    for (int i = 0; i < D_DIM / 4; i++) {
        float4 ev = eb4[i];
        op[(size_t)(4 * i + 0) * T_LEN] = ev.x;
        op[(size_t)(4 * i + 1) * T_LEN] = ev.y;
        op[(size_t)(4 * i + 2) * T_LEN] = ev.z;
        op[(size_t)(4 * i + 3) * T_LEN] = ev.w;
        float lo0, hi0, lo1, hi1;
        UNPACK_X2(lo0, hi0, xp[2 * i + 0]);
        UNPACK_X2(lo1, hi1, xp[2 * i + 1]);
        atomicAdd(dwp + 4 * i + 0, lo0);
        atomicAdd(dwp + 4 * i + 1, hi0);
        atomicAdd(dwp + 4 * i + 2, lo1);
        atomicAdd(dwp + 4 * i + 3, hi1);
    }
    atomicAdd(&g_counts[bestc], 1);
}

// new_embeddings[k][d] = dw[k][d] / cluster_size[k]
// n = sum(counts) == N_VEC exactly (sum of 2^17 ones, exact in fp32)
__global__ void finalize_kernel(float* __restrict__ out_emb) {
    int i = blockIdx.x * blockDim.x + threadIdx.x;
    if (i >= K_CODES * D_DIM) return;
    int c = i >> 6;
    float cnt = (float)g_counts[c];
    const float nf = (float)N_VEC;
    float cs = (cnt + 1e-5f) / (nf + (float)K_CODES * 1e-5f) * nf;
    out_emb[i] = g_dw[i] / cs;
}

extern "C" void kernel_launch(void* const* d_in, const int* in_sizes, int n_in,
                              void* d_out, int out_size) {
    const float* x   = (const float*)d_in[0];
    const float* emb = (const float*)d_in[1];
    float* out     = (float*)d_out;
    float* outq    = out;                                  // [B, D, T]
    float* out_emb = out + (size_t)N_VEC * D_DIM;          // [K, D]

    zero_kernel<<<(K_CODES * D_DIM + 255) / 256, 256>>>();
    enorm_kernel<<<(K_CODES + 255) / 256, 256>>>(emb);
    assign_kernel<<<N_VEC / TPB, TPB>>>(x, emb, outq);
    finalize_kernel<<<(K_CODES * D_DIM + 255) / 256, 256>>>(out_emb);
}

// round 7
// speedup vs baseline: 1.5100x; 1.5100x over previous
#include <cuda_runtime.h>

// Problem constants
#define K_CODES 1024
#define D_DIM   64
#define B_SZ    16
#define T_LEN   8192
#define N_VEC   (B_SZ * T_LEN)     // 131072 vectors
#define TPB     256
#define VV      128                // vectors per CTA
#define CH      64                 // codes per smem chunk

typedef unsigned long long u64;

// Packed fp32x2 ops (sm_103a; PTX-only, ptxas never auto-fuses)
#define FMA_X2(d, a, b, c) \
    asm("fma.rn.f32x2 %0, %1, %2, %3;" : "=l"(d) : "l"(a), "l"(b), "l"(c))
#define PACK_X2(d, lo, hi) \
    asm("mov.b64 %0, {%1, %2};" : "=l"(d) : "f"(lo), "f"(hi))
#define UNPACK_X2(lo, hi, s) \
    asm("mov.b64 {%0, %1}, %2;" : "=f"(lo), "=f"(hi) : "l"(s))
#define LDS_V2U64(p0, p1, addr) \
    asm("ld.shared.v2.u64 {%0, %1}, [%2];" : "=l"(p0), "=l"(p1) : "r"(addr))
#define LDS_V4F32(f0, f1, f2, f3, addr) \
    asm("ld.shared.v4.f32 {%0,%1,%2,%3}, [%4];" \
        : "=f"(f0), "=f"(f1), "=f"(f2), "=f"(f3) : "r"(addr))
#define STS_V4F32(addr, f0, f1, f2, f3) \
    asm volatile("st.shared.v4.f32 [%0], {%1,%2,%3,%4};" \
        :: "r"(addr), "f"(f0), "f"(f1), "f"(f2), "f"(f3))
#define LDS_F32(f, addr) \
    asm("ld.shared.f32 %0, [%1];" : "=f"(f) : "r"(addr))

// Scratch (allocation-free rule -> __device__ globals)
__device__ float g_dw[K_CODES * D_DIM];
__device__ int   g_counts[K_CODES];
__device__ float g_enorm[K_CODES];

// Dynamic smem layout (bytes) — exactly 48KB, no cudaFuncSetAttribute needed:
//   [0, 32768)       x tile: 64 d-rows x 512B (swizzled f32x2 vector-pairs)
//   [32768, 49152)   e tile: 64 code-rows x 256B (64 floats)
//   red2 (128 x u64 argmin cells) ALIASES the first 1KB of the e tile:
//   the e tile is dead after the last chunk's compute; a barrier separates.
#define XS_OFF   0
#define ES_OFF   32768
#define SMEM_BYTES 49152

__global__ void zero_kernel() {
    int i = blockIdx.x * blockDim.x + threadIdx.x;
    if (i < K_CODES * D_DIM) g_dw[i] = 0.0f;
    if (i < K_CODES)         g_counts[i] = 0;
}

__global__ void enorm_kernel(const float* __restrict__ emb) {
    int c = blockIdx.x * blockDim.x + threadIdx.x;
    if (c < K_CODES) {
        const float* e = emb + c * D_DIM;
        float s0 = 0.f, s1 = 0.f, s2 = 0.f, s3 = 0.f;
        #pragma unroll
        for (int d = 0; d < D_DIM; d += 4) {
            float v0 = e[d + 0], v1 = e[d + 1], v2 = e[d + 2], v3 = e[d + 3];
            s0 = fmaf(v0, v0, s0);
            s1 = fmaf(v1, v1, s1);
            s2 = fmaf(v2, v2, s2);
            s3 = fmaf(v3, v3, s3);
        }
        g_enorm[c] = (s0 + s1) + (s2 + s3);
    }
}

// GEMM-tiled assignment. CTA: 128 vectors x 1024 codes (chunks of 64).
// Thread (tv = tid&15, tc = tid>>4): micro-tile 8 vectors x 4 codes.
// Dot via fma.rn.f32x2 packed over vector pairs; e scalar duplicated (ALU).
// x tile stored as swizzled f32x2 pairs so the 16-lane 16B loads are 2-phase
// (each 16B bank-slot covered exactly twice) instead of 4-way conflicted.
// E-chunk global loads are register-prefetched one chunk ahead so their
// L2 latency hides behind the previous chunk's compute.
__global__ void __launch_bounds__(TPB, 2) assign_kernel(
    const float* __restrict__ x,
    const float* __restrict__ emb,
    float* __restrict__ outq)
{
    extern __shared__ char sm[];
    const unsigned sbase = (unsigned)__cvta_generic_to_shared(sm);
    const unsigned xs  = sbase + XS_OFF;
    const unsigned esb = sbase + ES_OFF;
    u64* red2 = (u64*)(sm + ES_OFF);   // aliases e tile (dead after main loop)

    const int tid = threadIdx.x;
    const int tv  = tid & 15;
    const int tc  = tid >> 4;
    const int blk = blockIdx.x;
    const int b   = blk >> 6;                 // 64 CTAs per batch row
    const int t0  = (blk << 7) & (T_LEN - 1); // 128 vectors per CTA

    // Load x tile: xs[d][swizzled pair columns].
    // Pair p lives at byte (((p&~1)<<3) ^ (((p>>4)&3)<<4)) + ((p&1)<<3).
    {
        const float* xb = x + ((size_t)(b << 6)) * T_LEN + t0;
        #pragma unroll
        for (int i4 = tid; i4 < (D_DIM * VV) / 4; i4 += TPB) {   // 2048 float4
            int d = i4 >> 5, v4 = i4 & 31;
            float4 val = *(const float4*)(xb + (size_t)d * T_LEN + v4 * 4);
            unsigned a = xs + d * 512 + (((unsigned)(v4 << 4)) ^ (((v4 >> 3) & 3) << 4));
            STS_V4F32(a, val.x, val.y, val.z, val.w);
        }
    }

    float best[8];
    int   bidx[8];
    #pragma unroll
    for (int k = 0; k < 8; k++) { best[k] = 3.402823466e38f; bidx[k] = 0; }

    // Per-thread swizzled x-line base: first 16B at xlane, second at xlane^16.
    const unsigned xlane = ((unsigned)(tv * 32)) ^ ((((unsigned)tv >> 2) & 3) << 4);

    // This thread's 4 float4 slots within each 1024-float4 e chunk.
    // Slot j: i4 = tid + j*TPB  ->  code row i4>>4, 16B column i4&15.
    float4 pf[4];
    #pragma unroll
    for (int j = 0; j < 4; j++) {
        int i4 = tid + j * TPB;
        pf[j] = *(const float4*)(emb + (size_t)(i4 >> 4) * D_DIM + (i4 & 15) * 4);
    }

    for (int c0 = 0; c0 < K_CODES; c0 += CH) {
        __syncthreads();   // prev chunk's compute (and x-tile stores) done
        #pragma unroll
        for (int j = 0; j < 4; j++) {
            int i4 = tid + j * TPB;
            STS_V4F32(esb + (i4 >> 4) * 256 + (i4 & 15) * 16,
                      pf[j].x, pf[j].y, pf[j].z, pf[j].w);
        }
        __syncthreads();

        // Prefetch next chunk; scoreboard wait lands at next STS (after
        // this chunk's compute) so the L2 latency is fully hidden.
        if (c0 + CH < K_CODES) {
            const float* nb = emb + (size_t)(c0 + CH) * D_DIM;
            #pragma unroll
            for (int j = 0; j < 4; j++) {
                int i4 = tid + j * TPB;
                pf[j] = *(const float4*)(nb + (size_t)(i4 >> 4) * D_DIM + (i4 & 15) * 4);
            }
        }

        u64 acc[4][4];   // [code][vector-pair]
        #pragma unroll
        for (int cc = 0; cc < 4; cc++)
            #pragma unroll
            for (int vp = 0; vp < 4; vp++) acc[cc][vp] = 0ull;

        #pragma unroll 4
        for (int d4 = 0; d4 < 16; d4++) {
            // x fragment: 4 d's x 4 vector-pairs (8 LDS.128 -> 16 u64)
            u64 xf[4][4];
            #pragma unroll
            for (int dd = 0; dd < 4; dd++) {
                unsigned a = xs + (d4 * 4 + dd) * 512 + xlane;
                LDS_V2U64(xf[dd][0], xf[dd][1], a);
                LDS_V2U64(xf[dd][2], xf[dd][3], a ^ 16);
            }
            #pragma unroll
            for (int cc = 0; cc < 4; cc++) {
                float e0, e1, e2, e3;
                LDS_V4F32(e0, e1, e2, e3, esb + (tc * 4 + cc) * 256 + d4 * 16);
                u64 ed0, ed1, ed2, ed3;
                PACK_X2(ed0, e0, e0);
                PACK_X2(ed1, e1, e1);
                PACK_X2(ed2, e2, e2);
                PACK_X2(ed3, e3, e3);
                #pragma unroll
                for (int vp = 0; vp < 4; vp++) {
                    FMA_X2(acc[cc][vp], ed0, xf[0][vp], acc[cc][vp]);
                    FMA_X2(acc[cc][vp], ed1, xf[1][vp], acc[cc][vp]);
                    FMA_X2(acc[cc][vp], ed2, xf[2][vp], acc[cc][vp]);
                    FMA_X2(acc[cc][vp], ed3, xf[3][vp], acc[cc][vp]);
                }
            }
        }

        // Scores + running argmin (codes ascending; strict < keeps first min)
        #pragma unroll
        for (int cc = 0; cc < 4; cc++) {
            int c = c0 + tc * 4 + cc;
            float enc = __ldg(&g_enorm[c]);
            #pragma unroll
            for (int vp = 0; vp < 4; vp++) {
                float d0, d1;
                UNPACK_X2(d0, d1, acc[cc][vp]);
                float s0 = fmaf(-2.0f, d0, enc);
                float s1 = fmaf(-2.0f, d1, enc);
                if (s0 < best[2 * vp])     { best[2 * vp]     = s0; bidx[2 * vp]     = c; }
                if (s1 < best[2 * vp + 1]) { best[2 * vp + 1] = s1; bidx[2 * vp + 1] = c; }
            }
        }
    }

    // e tile is dead now; reuse its first KB for the argmin cells.
    __syncthreads();
    if (tid < VV) red2[tid] = 0xFFFFFFFFFFFFFFFFull;
    __syncthreads();

    // Cross-thread argmin: lexicographic (score, idx) via packed u64 atomicMin.
    // ordered-uint encoding of fp32 preserves <; low bits carry code index so
    // exact ties resolve to the smallest index (jnp.argmin semantics).
    #pragma unroll
    for (int k = 0; k < 8; k++) {
        unsigned fb = __float_as_uint(best[k]);
        fb = (fb & 0x80000000u) ? ~fb : (fb | 0x80000000u);
        u64 key = ((u64)fb << 32) | (unsigned)bidx[k];
        atomicMin(&red2[tv * 8 + k], key);
    }
    __syncthreads();

    // Epilogue: thread v < 128 owns vector v.
    if (tid < VV) {
        const int v = tid;
        const int c = (int)(red2[v] & 1023u);
        atomicAdd(&g_counts[c], 1);

        const float4* er4 = (const float4*)(emb + (size_t)c * D_DIM);
        float* op  = outq + ((size_t)(b << 6)) * T_LEN + t0 + v;
        float* dwp = g_dw + (size_t)c * D_DIM;

        const int p = v >> 1;
        const unsigned fbyte = ((((unsigned)(p & ~1)) << 3) ^ ((((unsigned)p >> 4) & 3) << 4))
                             + (((unsigned)(p & 1)) << 3) + (((unsigned)(v & 1)) << 2);
        #pragma unroll
        for (int i = 0; i < D_DIM / 4; i++) {
            float4 ev = er4[i];
            op[(size_t)(4 * i + 0) * T_LEN] = ev.x;
            op[(size_t)(4 * i + 1) * T_LEN] = ev.y;
            op[(size_t)(4 * i + 2) * T_LEN] = ev.z;
            op[(size_t)(4 * i + 3) * T_LEN] = ev.w;
            #pragma unroll
            for (int dd = 0; dd < 4; dd++) {
                float xv;
                LDS_F32(xv, xs + (4 * i + dd) * 512 + fbyte);
                atomicAdd(dwp + 4 * i + dd, xv);
            }
        }
    }
}

// new_embeddings[k][d] = dw[k][d] / cluster_size[k]
// n = sum(counts) == N_VEC exactly (sum of 2^17 ones, exact in fp32)
__global__ void finalize_kernel(float* __restrict__ out_emb) {
    int i = blockIdx.x * blockDim.x + threadIdx.x;
    if (i >= K_CODES * D_DIM) return;
    int c = i >> 6;
    float cnt = (float)g_counts[c];
    const float nf = (float)N_VEC;
    float cs = (cnt + 1e-5f) / (nf + (float)K_CODES * 1e-5f) * nf;
    out_emb[i] = g_dw[i] / cs;
}

extern "C" void kernel_launch(void* const* d_in, const int* in_sizes, int n_in,
                              void* d_out, int out_size) {
    const float* x   = (const float*)d_in[0];
    const float* emb = (const float*)d_in[1];
    float* out     = (float*)d_out;
    float* outq    = out;                                  // [B, D, T]
    float* out_emb = out + (size_t)N_VEC * D_DIM;          // [K, D]

    zero_kernel<<<(K_CODES * D_DIM + 255) / 256, 256>>>();
    enorm_kernel<<<(K_CODES + 255) / 256, 256>>>(emb);
    assign_kernel<<<N_VEC / VV, TPB, SMEM_BYTES>>>(x, emb, outq);
    finalize_kernel<<<(K_CODES * D_DIM + 255) / 256, 256>>>(out_emb);
}

// round 9
// speedup vs baseline: 1.5659x; 1.0371x over previous
#include <cuda_runtime.h>

// Problem constants
#define K_CODES 1024
#define D_DIM   64
#define B_SZ    16
#define T_LEN   8192
#define N_VEC   (B_SZ * T_LEN)     // 131072 vectors
#define TPB     256
#define VV      128                // vectors per CTA
#define CH      64                 // codes per smem chunk

typedef unsigned long long u64;

// Packed fp32x2 ops (sm_103a; PTX-only, ptxas never auto-fuses)
#define FMA_X2(d, a, b, c) \
    asm("fma.rn.f32x2 %0, %1, %2, %3;" : "=l"(d) : "l"(a), "l"(b), "l"(c))
#define PACK_X2(d, lo, hi) \
    asm("mov.b64 %0, {%1, %2};" : "=l"(d) : "f"(lo), "f"(hi))
#define UNPACK_X2(lo, hi, s) \
    asm("mov.b64 {%0, %1}, %2;" : "=f"(lo), "=f"(hi) : "l"(s))
#define LDS_V2U64(p0, p1, addr) \
    asm("ld.shared.v2.u64 {%0, %1}, [%2];" : "=l"(p0), "=l"(p1) : "r"(addr))
#define LDS_V2F32(f0, f1, addr) \
    asm("ld.shared.v2.f32 {%0, %1}, [%2];" : "=f"(f0), "=f"(f1) : "r"(addr))
#define STS_V4F32(addr, f0, f1, f2, f3) \
    asm volatile("st.shared.v4.f32 [%0], {%1,%2,%3,%4};" \
        :: "r"(addr), "f"(f0), "f"(f1), "f"(f2), "f"(f3))
#define LDS_F32(f, addr) \
    asm("ld.shared.f32 %0, [%1];" : "=f"(f) : "r"(addr))
// Vector float reduction (sm_90+ baseline; no arch-'a' feature needed)
#define REDG_ADD_V4F32(ptr, a0, a1, a2, a3) \
    asm volatile("red.global.add.v4.f32 [%0], {%1,%2,%3,%4};" \
        :: "l"(ptr), "f"(a0), "f"(a1), "f"(a2), "f"(a3) : "memory")

// Scratch (allocation-free rule -> __device__ globals)
__device__ float g_dw[K_CODES * D_DIM];
__device__ int   g_counts[K_CODES];
__device__ float g_enorm[K_CODES];

// Dynamic smem layout (bytes) — exactly 48KB, no cudaFuncSetAttribute needed:
//   [0, 32768)       x tile: 64 d-rows x 512B (swizzled f32x2 vector-pairs)
//   [32768, 49152)   e tile: 64 code-rows x 256B (64 floats)
//   red2 (128 x u64 argmin cells) ALIASES the first 1KB of the e tile:
//   the e tile is dead after the last chunk's compute; a barrier separates.
#define XS_OFF   0
#define ES_OFF   32768
#define SMEM_BYTES 49152

// Fused init: zero dw/counts + code norms. 65536 threads.
__global__ void init_kernel(const float* __restrict__ emb) {
    int i = blockIdx.x * blockDim.x + threadIdx.x;
    if (i < K_CODES * D_DIM) g_dw[i] = 0.0f;
    if (i < K_CODES) {
        g_counts[i] = 0;
        const float* e = emb + i * D_DIM;
        float s0 = 0.f, s1 = 0.f, s2 = 0.f, s3 = 0.f;
        #pragma unroll
        for (int d = 0; d < D_DIM; d += 4) {
            float v0 = e[d], v1 = e[d+1], v2 = e[d+2], v3 = e[d+3];
            s0 = fmaf(v0, v0, s0); s1 = fmaf(v1, v1, s1);
            s2 = fmaf(v2, v2, s2); s3 = fmaf(v3, v3, s3);
        }
        g_enorm[i] = (s0 + s1) + (s2 + s3);
    }
}

// GEMM-tiled assignment. CTA: 128 vectors x 1024 codes (chunks of 64).
// Thread (tv = tid&15, tc = tid>>4): micro-tile 8 vectors x 4 codes.
// Dot via fma.rn.f32x2 packed over vector pairs; e scalar duplicated (ALU).
// d-loop at 2-d granularity to keep live registers ~100 (no spills under
// the 2-CTA/SM occupancy bound). E-chunk globals reg-prefetched one chunk
// ahead so L2 latency hides behind compute.
__global__ void __launch_bounds__(TPB, 2) assign_kernel(
    const float* __restrict__ x,
    const float* __restrict__ emb,
    float* __restrict__ outq)
{
    extern __shared__ char sm[];
    const unsigned sbase = (unsigned)__cvta_generic_to_shared(sm);
    const unsigned xs  = sbase + XS_OFF;
    const unsigned esb = sbase + ES_OFF;
    u64* red2 = (u64*)(sm + ES_OFF);   // aliases e tile (dead after main loop)

    const int tid = threadIdx.x;
    const int tv  = tid & 15;
    const int tc  = tid >> 4;
    const int blk = blockIdx.x;
    const int b   = blk >> 6;                 // 64 CTAs per batch row
    const int t0  = (blk << 7) & (T_LEN - 1); // 128 vectors per CTA

    // Load x tile: xs[d][swizzled pair columns].
    // Pair p lives at byte (((p&~1)<<3) ^ (((p>>4)&3)<<4)) + ((p&1)<<3).
    {
        const float* xb = x + ((size_t)(b << 6)) * T_LEN + t0;
        #pragma unroll
        for (int i4 = tid; i4 < (D_DIM * VV) / 4; i4 += TPB) {   // 2048 float4
            int d = i4 >> 5, v4 = i4 & 31;
            float4 val = *(const float4*)(xb + (size_t)d * T_LEN + v4 * 4);
            unsigned a = xs + d * 512 + (((unsigned)(v4 << 4)) ^ (((v4 >> 3) & 3) << 4));
            STS_V4F32(a, val.x, val.y, val.z, val.w);
        }
    }

    float best[8];
    int   bidx[8];
    #pragma unroll
    for (int k = 0; k < 8; k++) { best[k] = 3.402823466e38f; bidx[k] = 0; }

    // Per-thread swizzled x-line base: first 16B at xlane, second at xlane^16.
    const unsigned xlane = ((unsigned)(tv * 32)) ^ ((((unsigned)tv >> 2) & 3) << 4);

    // This thread's 4 float4 slots within each 1024-float4 e chunk.
    const float4* emb4 = (const float4*)emb;
    float4 pf[4];
    #pragma unroll
    for (int j = 0; j < 4; j++)
        pf[j] = emb4[(size_t)(tid + j * TPB)];

    for (int c0 = 0; c0 < K_CODES; c0 += CH) {
        __syncthreads();   // prev chunk's compute (and x-tile stores) done
        #pragma unroll
        for (int j = 0; j < 4; j++) {
            int i4 = tid + j * TPB;
            STS_V4F32(esb + (i4 >> 4) * 256 + (i4 & 15) * 16,
                      pf[j].x, pf[j].y, pf[j].z, pf[j].w);
        }
        __syncthreads();

        // Prefetch next chunk; scoreboard wait lands at next STS (after
        // this chunk's compute) so the L2 latency is fully hidden.
        if (c0 + CH < K_CODES) {
            const float4* nb = emb4 + ((size_t)(c0 + CH) << 4);
            #pragma unroll
            for (int j = 0; j < 4; j++)
                pf[j] = nb[(size_t)(tid + j * TPB)];
        }

        u64 acc[4][4];   // [code][vector-pair]
        #pragma unroll
        for (int cc = 0; cc < 4; cc++)
            #pragma unroll
            for (int vp = 0; vp < 4; vp++) acc[cc][vp] = 0ull;

        #pragma unroll 4
        for (int d2 = 0; d2 < 32; d2++) {     // 2 d's per iteration
            u64 xf[2][4];
            #pragma unroll
            for (int dd = 0; dd < 2; dd++) {
                unsigned a = xs + (d2 * 2 + dd) * 512 + xlane;
                LDS_V2U64(xf[dd][0], xf[dd][1], a);
                LDS_V2U64(xf[dd][2], xf[dd][3], a ^ 16);
            }
            #pragma unroll
            for (int cc = 0; cc < 4; cc++) {
                float e0, e1;
                LDS_V2F32(e0, e1, esb + (tc * 4 + cc) * 256 + d2 * 8);
                u64 ed0, ed1;
                PACK_X2(ed0, e0, e0);
                PACK_X2(ed1, e1, e1);
                #pragma unroll
                for (int vp = 0; vp < 4; vp++) {
                    FMA_X2(acc[cc][vp], ed0, xf[0][vp], acc[cc][vp]);
                    FMA_X2(acc[cc][vp], ed1, xf[1][vp], acc[cc][vp]);
                }
            }
        }

        // Scores + running argmin (codes ascending; strict < keeps first min)
        #pragma unroll
        for (int cc = 0; cc < 4; cc++) {
            int c = c0 + tc * 4 + cc;
            float enc = __ldg(&g_enorm[c]);
            #pragma unroll
            for (int vp = 0; vp < 4; vp++) {
                float d0, d1;
                UNPACK_X2(d0, d1, acc[cc][vp]);
                float s0 = fmaf(-2.0f, d0, enc);
                float s1 = fmaf(-2.0f, d1, enc);
                if (s0 < best[2 * vp])     { best[2 * vp]     = s0; bidx[2 * vp]     = c; }
                if (s1 < best[2 * vp + 1]) { best[2 * vp + 1] = s1; bidx[2 * vp + 1] = c; }
            }
        }
    }

    // e tile is dead now; reuse its first KB for the argmin cells.
    __syncthreads();
    if (tid < VV) red2[tid] = 0xFFFFFFFFFFFFFFFFull;
    __syncthreads();

    // Cross-thread argmin: lexicographic (score, idx) via packed u64 atomicMin.
    // ordered-uint encoding of fp32 preserves <; low bits carry code index so
    // exact ties resolve to the smallest index (jnp.argmin semantics).
    #pragma unroll
    for (int k = 0; k < 8; k++) {
        unsigned fb = __float_as_uint(best[k]);
        fb = (fb & 0x80000000u) ? ~fb : (fb | 0x80000000u);
        u64 key = ((u64)fb << 32) | (unsigned)bidx[k];
        atomicMin(&red2[tv * 8 + k], key);
    }
    __syncthreads();

    // Epilogue: thread v < 128 owns vector v.
    if (tid < VV) {
        const int v = tid;
        const int c = (int)(red2[v] & 1023u);
        atomicAdd(&g_counts[c], 1);

        const float4* er4 = (const float4*)(emb + (size_t)c * D_DIM);
        float* op  = outq + ((size_t)(b << 6)) * T_LEN + t0 + v;
        float* dwp = g_dw + (size_t)c * D_DIM;

        const int p = v >> 1;
        const unsigned fbyte = ((((unsigned)(p & ~1)) << 3) ^ ((((unsigned)p >> 4) & 3) << 4))
                             + (((unsigned)(p & 1)) << 3) + (((unsigned)(v & 1)) << 2);
        #pragma unroll
        for (int i = 0; i < D_DIM / 4; i++) {
            float4 ev = er4[i];
            op[(size_t)(4 * i + 0) * T_LEN] = ev.x;
            op[(size_t)(4 * i + 1) * T_LEN] = ev.y;
            op[(size_t)(4 * i + 2) * T_LEN] = ev.z;
            op[(size_t)(4 * i + 3) * T_LEN] = ev.w;
            float x0, x1, x2, x3;
            LDS_F32(x0, xs + (4 * i + 0) * 512 + fbyte);
            LDS_F32(x1, xs + (4 * i + 1) * 512 + fbyte);
            LDS_F32(x2, xs + (4 * i + 2) * 512 + fbyte);
            LDS_F32(x3, xs + (4 * i + 3) * 512 + fbyte);
            REDG_ADD_V4F32(dwp + 4 * i, x0, x1, x2, x3);
        }
    }
}

// new_embeddings[k][d] = dw[k][d] / cluster_size[k]
// n = sum(counts) == N_VEC exactly (sum of 2^17 ones, exact in fp32)
__global__ void finalize_kernel(float* __restrict__ out_emb) {
    int i = blockIdx.x * blockDim.x + threadIdx.x;
    if (i >= K_CODES * D_DIM) return;
    int c = i >> 6;
    float cnt = (float)g_counts[c];
    const float nf = (float)N_VEC;
    float cs = (cnt + 1e-5f) / (nf + (float)K_CODES * 1e-5f) * nf;
    out_emb[i] = g_dw[i] / cs;
}

extern "C" void kernel_launch(void* const* d_in, const int* in_sizes, int n_in,
                              void* d_out, int out_size) {
    const float* x   = (const float*)d_in[0];
    const float* emb = (const float*)d_in[1];
    float* out     = (float*)d_out;
    float* outq    = out;                                  // [B, D, T]
    float* out_emb = out + (size_t)N_VEC * D_DIM;          // [K, D]

    init_kernel<<<(K_CODES * D_DIM + 255) / 256, 256>>>(emb);
    assign_kernel<<<N_VEC / VV, TPB, SMEM_BYTES>>>(x, emb, outq);
    finalize_kernel<<<(K_CODES * D_DIM + 255) / 256, 256>>>(out_emb);
}